// round 17
// baseline (speedup 1.0000x reference)
#include <cuda_runtime.h>
#include <math.h>

#define NB 32
#define NT 36
#define NN 10000
#define NF 3
#define NH 10
#define NR 20
#define PRED_ELEMS (NB * NH * NN)   // 3,200,000
#define NBLK_X ((NN + 255) / 256)   // 40
#define NBLOCKS (NBLK_X * NB)       // 1280

// ---------------- device scratch (zero-initialized at module load; ----------------
// ---------------- last block restores zeros every launch -> replay-safe) ----------
__device__ float g_time_mean[NB * NN];   // [B, N]; may contain NaN
__device__ float g_rsum[NB * NR];
__device__ float g_rcnt[NB * NR];
__device__ float g_g1;                   // global nanmean of pred (k2 reads it)
__device__ unsigned int g_done;

// ---------------- K1: read-dominated pass (NO bulk output writes) ----------------
// grid (40, 32), block 256; one thread per (b, n). Scalar stride-12B loads
// (warp covers 384 contiguous B per t -> optimal L1 wavefronts). Writes only
// 1.28 MB of time_means; the 12.8 MB broadcast happens in K2 so the DRAM bus
// stays in read mode (R6-R13 evidence: interleaved writes pin reads at
// ~4.6 TB/s; R1's write-free read pass back-computes to ~6.5 TB/s).
__global__ void __launch_bounds__(256) k1_reduce(
    const float* __restrict__ seq, const int* __restrict__ cid32,
    float* __restrict__ out) {
    const int b = blockIdx.y;
    const int n = blockIdx.x * blockDim.x + threadIdx.x;
    const int tid = threadIdx.x;

    __shared__ float s_rsum[NR];
    __shared__ float s_rcnt[NR];
    if (tid < NR) { s_rsum[tid] = 0.0f; s_rcnt[tid] = 0.0f; }

    // int64-vs-int32 probe for cluster_id (if int64, all odd words are 0;
    // values 0..19 -> misfire P = 20^-64).
    int bad = 0;
    if (tid < 64) bad = (cid32[2 * tid + 1] != 0);
    const int is64 = (__syncthreads_or(bad) == 0);   // also covers smem init sync

    if (n < NN) {
        const float* base = seq + (size_t)b * (NT * NN * NF) + (size_t)n * NF;
        float s = 0.0f, c = 0.0f;
#pragma unroll
        for (int t = 0; t < NT; t++) {
            float x = __ldg(base + (size_t)t * (NN * NF));
            if (x == x) { s += x; c += 1.0f; }
        }
        const float tm = s / c;             // 0/0 -> NaN when node all-NaN
        g_time_mean[b * NN + n] = tm;       // small write (1.28 MB total)

        if (tm == tm) {
            const int r = is64 ? cid32[2 * n] : cid32[n];
            atomicAdd(&s_rsum[r], tm);
            atomicAdd(&s_rcnt[r], 1.0f);
        }
        // all-NaN cells need no list: K2 tests tm==tm directly
    }
    __syncthreads();
    if (tid < NR) {
        atomicAdd(&g_rsum[b * NR + tid], s_rsum[tid]);
    } else if (tid < 2 * NR) {
        const int r = tid - NR;
        atomicAdd(&g_rcnt[b * NR + r], s_rcnt[r]);
    }

    // ---------------- last-block finalization ----------------
    __threadfence();
    __shared__ unsigned int s_ticket;
    __syncthreads();
    if (tid == 0) s_ticket = atomicAdd(&g_done, 1u);
    __syncthreads();
    if (s_ticket != NBLOCKS - 1) return;

    // v0/v1 -> g1 (valid-node sum/count); v2/v3 -> g2 (mean of valid regional)
    float v0 = 0.f, v1 = 0.f, v2 = 0.f, v3 = 0.f;
    for (int i = tid; i < NB * NR; i += 256) {
        const float rs = g_rsum[i];
        const float rc = g_rcnt[i];
        const float reg = rs / rc;
        v0 += rs; v1 += rc;
        if (reg == reg) { v2 += reg; v3 += 1.0f; }
    }
#pragma unroll
    for (int o = 16; o > 0; o >>= 1) {
        v0 += __shfl_down_sync(0xFFFFFFFFu, v0, o);
        v1 += __shfl_down_sync(0xFFFFFFFFu, v1, o);
        v2 += __shfl_down_sync(0xFFFFFFFFu, v2, o);
        v3 += __shfl_down_sync(0xFFFFFFFFu, v3, o);
    }
    __shared__ float sw[8][4];
    const int w = tid >> 5, l = tid & 31;
    if (l == 0) { sw[w][0] = v0; sw[w][1] = v1; sw[w][2] = v2; sw[w][3] = v3; }
    __syncthreads();
    __shared__ float s_g1, s_g2;
    if (w == 0) {
        float a0 = (l < 8) ? sw[l][0] : 0.0f;
        float a1 = (l < 8) ? sw[l][1] : 0.0f;
        float a2 = (l < 8) ? sw[l][2] : 0.0f;
        float a3 = (l < 8) ? sw[l][3] : 0.0f;
#pragma unroll
        for (int o = 4; o > 0; o >>= 1) {
            a0 += __shfl_down_sync(0xFFFFFFFFu, a0, o);
            a1 += __shfl_down_sync(0xFFFFFFFFu, a1, o);
            a2 += __shfl_down_sync(0xFFFFFFFFu, a2, o);
            a3 += __shfl_down_sync(0xFFFFFFFFu, a3, o);
        }
        if (l == 0) { s_g1 = a0 / a1; s_g2 = a2 / a3; }
    }
    __syncthreads();
    if (tid == 0) g_g1 = s_g1;              // K2 needs it for NaN backfill
    const float g2 = s_g2;

    // regional output (NaN regions -> g2), then re-zero accumulators
    float* outR = out + PRED_ELEMS;
    for (int i = tid; i < NB * NR; i += 256) {
        const int bb = i / NR, rr = i % NR;
        const float reg = g_rsum[i] / g_rcnt[i];
        const float val = (reg == reg) ? reg : g2;
#pragma unroll
        for (int h = 0; h < NH; h++) {
            outR[(bb * NH + h) * NR + rr] = val;
        }
        g_rsum[i] = 0.0f;
        g_rcnt[i] = 0.0f;
    }
    if (tid == 0) g_done = 0;
}

// ---------------- K2: pure write burst (12.8 MB out_pred) ----------------
// grid (10, 32), block 256; each thread owns 4 nodes (one float4 of tm).
// tm is L2-hot (just written). NaN cells -> g1 inline. Warp stores 4 KB
// contiguous per h-slice -> maximal write coalescing, single bus direction.
__global__ void __launch_bounds__(256) k2_broadcast(float* __restrict__ out) {
    const int b = blockIdx.y;
    const int q = blockIdx.x * blockDim.x + threadIdx.x;   // float4-group index
    if (q >= NN / 4) return;
    const float g1 = g_g1;

    float4 tm = *(const float4*)&g_time_mean[b * NN + 4 * q];
    if (!(tm.x == tm.x)) tm.x = g1;
    if (!(tm.y == tm.y)) tm.y = g1;
    if (!(tm.z == tm.z)) tm.z = g1;
    if (!(tm.w == tm.w)) tm.w = g1;

#pragma unroll
    for (int h = 0; h < NH; h++) {
        *(float4*)&out[(size_t)(b * NH + h) * NN + 4 * q] = tm;
    }
}

// ---------------- launcher ----------------
extern "C" void kernel_launch(void* const* d_in, const int* in_sizes, int n_in,
                              void* d_out, int out_size) {
    const float* seq = (const float*)d_in[0];
    const int* cid = (const int*)d_in[1];   // int32 or int64 -- probed in-kernel
    float* out = (float*)d_out;

    dim3 grid1(NBLK_X, NB);
    k1_reduce<<<grid1, 256>>>(seq, cid, out);

    dim3 grid2((NN / 4 + 255) / 256, NB);   // (10, 32)
    k2_broadcast<<<grid2, 256>>>(out);
}